// round 15
// baseline (speedup 1.0000x reference)
#include <cuda_runtime.h>
#include <cuda_fp16.h>
#include <mma.h>
#include <cstdint>

using namespace nvcuda;

#define NROWS  200000
#define CCH    128
#define TM     128
#define TK     64                      // K-chunk (fp16 row = 128B)
#define NCHNK  6                       // K = 384 = 6 x 64
#define NBLK1  1563                    // ceil(200000/128)
#define BN_EPS 1e-5f

#define A_LD   72                      // halves (144B rows)
#define B_LD   136                     // halves (272B rows)
#define A_BYTES (TM * A_LD * 2)        // 18432
#define B_BYTES (TK * B_LD * 2)        // 17408
#define BUF_STRIDE (A_BYTES + B_BYTES) // 35840
#define NSTAGE 3
#define DYN_SMEM (NSTAGE * BUF_STRIDE) // 107520 (fp32 stage 64KB fits inside)

// ---------------- global scratch (allocation-free) ----------------
__device__ __half g_featH[(size_t)NROWS * CCH];          // 51.2 MB fp16 features
__device__ __half g_Wh   [9 * CCH * CCH];                // fp16 W [a*3+seg][k][n]
__device__ __half g_out  [(size_t)3 * NROWS * CCH];      // 153.6 MB fp16 pre-BN outputs
__device__ float  g_part [(size_t)3 * NBLK1 * 2 * CCH];  // per-tile col {sum,sumsq}
__device__ float  g_scale[3 * CCH];                      // rstd*gamma
__device__ float  g_off  [3 * CCH];                      // beta - mu*rstd*gamma

// ---------------- helpers ----------------
__device__ __forceinline__ uint32_t smem_u32(const void* p) {
    return (uint32_t)__cvta_generic_to_shared(p);
}
__device__ __forceinline__ void cp16(uint32_t dst, const void* src, uint32_t sz) {
    asm volatile("cp.async.cg.shared.global [%0], [%1], 16, %2;"
                 :: "r"(dst), "l"(src), "r"(sz) : "memory");
}
__device__ __forceinline__ void cp_commit() {
    asm volatile("cp.async.commit_group;" ::: "memory");
}
__device__ __forceinline__ void cp_wait0() {
    asm volatile("cp.async.wait_group 0;" ::: "memory");
}
__device__ __forceinline__ void cp_wait1() {
    asm volatile("cp.async.wait_group 1;" ::: "memory");
}

// ---------------------------------------------------------------------------
// K0: fp32 -> fp16 preconversion for features (blocks < 25000) and W (rest)
// ---------------------------------------------------------------------------
__global__ __launch_bounds__(256) void k0_prep(const float* __restrict__ feat,
                                               const float* __restrict__ W)
{
    size_t i = (size_t)blockIdx.x * 256 + threadIdx.x;
    const size_t nfeat = (size_t)NROWS * CCH / 4;
    const float* src; __half* dst; size_t j;
    if (i < nfeat) { src = feat; dst = g_featH; j = i; }
    else           { src = W;    dst = g_Wh;    j = i - nfeat; if (j >= 9*CCH*CCH/4) return; }
    float4 v = ((const float4*)src)[j];
    __half2 h0 = __floats2half2_rn(v.x, v.y);
    __half2 h1 = __floats2half2_rn(v.z, v.w);
    *(uint2*)(dst + j * 4) = make_uint2(*(uint32_t*)&h0, *(uint32_t*)&h1);
}

// ---------------------------------------------------------------------------
// K1: per (axis, 128-row tile): out = sum_seg gather(A_seg) @ W[a,seg]
// fp16 wmma m16n16k16, K in 6 chunks of 64, 3-stage cp.async pipeline.
// (byte-identical to the 332.5us R11 kernel)
// ---------------------------------------------------------------------------
__global__ void __launch_bounds__(256, 2)
k1_gemm(const int* __restrict__ nb)
{
    const int a    = blockIdx.y;
    const int row0 = blockIdx.x * TM;
    const int t    = threadIdx.x;
    const int warp = t >> 5;
    const int mg   = warp >> 2;     // 0..1 : 64-row half
    const int ng   = warp & 3;      // 0..3 : 32-col group

    extern __shared__ __align__(1024) char dyn[];
    const uint32_t base32 = smem_u32(dyn);

    __shared__ int   s_idx[3][TM];
    __shared__ float Pred[512];

    if (t < TM) {
        int gr = row0 + t;
        bool ok = gr < NROWS;
        s_idx[1][t] = ok ? gr : NROWS;
        s_idx[0][t] = ok ? nb[(size_t)(a * 2 + 0) * NROWS + gr] : NROWS;
        s_idx[2][t] = ok ? nb[(size_t)(a * 2 + 1) * NROWS + gr] : NROWS;
    }
    __syncthreads();

    auto load_chunk = [&](int i) {
        const int seg = i >> 1;
        const int kk  = (i & 1) * TK;
        const int buf = i % NSTAGE;
        const uint32_t abase = base32 + buf * BUF_STRIDE;
        const uint32_t bbase = abase + A_BYTES;
#pragma unroll
        for (int it = 0; it < 4; it++) {
            int vid = t + it * 256;
            int r   = vid >> 3;
            int c   = vid & 7;
            int idx = s_idx[seg][r];
            uint32_t sz = (idx < NROWS) ? 16u : 0u;
            cp16(abase + r * (A_LD * 2) + c * 16,
                 g_featH + (size_t)idx * CCH + kk + c * 8, sz);
        }
        const __half* wsrc = g_Wh + ((size_t)(a * 3 + seg) * CCH + kk) * CCH;
#pragma unroll
        for (int it = 0; it < 4; it++) {
            int vid = t + it * 256;
            int r   = vid >> 4;
            int c   = vid & 15;
            cp16(bbase + r * (B_LD * 2) + c * 16, wsrc + r * CCH + c * 8, 16u);
        }
        cp_commit();
    };

    wmma::fragment<wmma::accumulator, 16, 16, 16, float> acc[4][2];
#pragma unroll
    for (int i = 0; i < 4; i++)
#pragma unroll
        for (int j = 0; j < 2; j++) wmma::fill_fragment(acc[i][j], 0.0f);

    load_chunk(0);
    load_chunk(1);

    for (int i = 0; i < NCHNK; i++) {
        if (i < NCHNK - 1) cp_wait1(); else cp_wait0();
        __syncthreads();
        if (i + 2 < NCHNK) load_chunk(i + 2);

        const int buf = i % NSTAGE;
        const half* As = (const half*)(dyn + buf * BUF_STRIDE);
        const half* Bs = (const half*)(dyn + buf * BUF_STRIDE + A_BYTES);
#pragma unroll
        for (int ks = 0; ks < 4; ks++) {
            wmma::fragment<wmma::matrix_a, 16, 16, 16, half, wmma::row_major> af[4];
#pragma unroll
            for (int q = 0; q < 4; q++)
                wmma::load_matrix_sync(af[q], As + (mg * 64 + q * 16) * A_LD + ks * 16, A_LD);
#pragma unroll
            for (int j = 0; j < 2; j++) {
                wmma::fragment<wmma::matrix_b, 16, 16, 16, half, wmma::row_major> bf;
                wmma::load_matrix_sync(bf, Bs + (ks * 16) * B_LD + ng * 32 + j * 16, B_LD);
#pragma unroll
                for (int q = 0; q < 4; q++)
                    wmma::mma_sync(acc[q][j], af[q], bf, acc[q][j]);
            }
        }
    }
    __syncthreads();

    // ---- epilogue: fp32 stage in smem (reuses pipeline buffers)
    float* stage = (float*)dyn;               // [128][128] fp32 = 64KB
#pragma unroll
    for (int q = 0; q < 4; q++)
#pragma unroll
        for (int j = 0; j < 2; j++)
            wmma::store_matrix_sync(stage + (mg * 64 + q * 16) * CCH + ng * 32 + j * 16,
                                    acc[q][j], CCH, wmma::mem_row_major);
    __syncthreads();

    const int valid = min(TM, NROWS - row0);

    {
        int col = t & 127, part = t >> 7;
        float s = 0.f, s2 = 0.f;
        const float* p = stage + col;
#pragma unroll 8
        for (int r = part * 64; r < part * 64 + 64; r++) {
            float v = p[r * CCH];
            s += v; s2 += v * v;
        }
        Pred[part * 256 + col]       = s;
        Pred[part * 256 + 128 + col] = s2;
    }
    {
        __half* gp = g_out + ((size_t)a * NROWS + row0) * CCH;
#pragma unroll
        for (int it = 0; it < 16; it++) {
            int vid = t + it * 256;
            int r   = vid >> 5;
            int u   = vid & 31;
            if (r < valid) {
                const float* sp = stage + r * CCH + u * 4;
                __half2 h0 = __floats2half2_rn(sp[0], sp[1]);
                __half2 h1 = __floats2half2_rn(sp[2], sp[3]);
                *(uint2*)(gp + (size_t)r * CCH + u * 4) =
                    make_uint2(*(uint32_t*)&h0, *(uint32_t*)&h1);
            }
        }
    }
    __syncthreads();
    if (t < CCH) {
        g_part[(((size_t)a * NBLK1 + blockIdx.x) * 2 + 0) * CCH + t] = Pred[t] + Pred[256 + t];
        g_part[(((size_t)a * NBLK1 + blockIdx.x) * 2 + 1) * CCH + t] = Pred[128 + t] + Pred[384 + t];
    }
}

// ---------------------------------------------------------------------------
// K2: single-kernel deterministic BN reduction.
// 3 blocks x 1024 threads. Item = (s,c) pair (256 items); 4 threads per item
// reduce fixed disjoint block ranges into sfloat; fixed-order double combine
// into a separate aligned staging array.
// ---------------------------------------------------------------------------
__global__ __launch_bounds__(1024) void k2_stats(const float* __restrict__ gamma,
                                                 const float* __restrict__ beta)
{
    const int a    = blockIdx.x;
    const int t    = threadIdx.x;
    const int item = t & 255;            // (s<<7)|c
    const int sub  = t >> 8;             // 0..3
    const int s    = item >> 7, c = item & 127;

    __shared__ float sfloat[4][256];
    __shared__ __align__(16) double sdbl[256];

    // sub-range: [sub*391, min(...,NBLK1))  (4*391 = 1564 >= 1563)
    const int b0 = sub * 391;
    const int b1 = min(b0 + 391, NBLK1);
    float acc = 0.f;
    for (int b = b0; b < b1; b++)
        acc += g_part[(((size_t)a * NBLK1 + b) * 2 + s) * CCH + c];
    sfloat[sub][item] = acc;
    __syncthreads();

    if (t < 256) {
        sdbl[item] = ((double)sfloat[0][item] + (double)sfloat[1][item])
                   + ((double)sfloat[2][item] + (double)sfloat[3][item]);
    }
    __syncthreads();

    if (t < CCH) {
        double sum = sdbl[t];            // s=0 partials
        double sq  = sdbl[128 + t];      // s=1 partials
        double mu  = sum / (double)NROWS;
        double var = sq / (double)NROWS - mu * mu;
        float rstd = rsqrtf((float)var + BN_EPS);
        float sc   = rstd * gamma[a * CCH + t];
        g_scale[a * CCH + t] = sc;
        g_off  [a * CCH + t] = beta[a * CCH + t] - (float)mu * sc;
    }
}

// ---------------------------------------------------------------------------
// K3: out = featH * sum_a sigmoid(o_a * sc[a] + off[a])
// 512 threads, 2 float4-groups per thread. Grid: 6.4M groups / 1024 = 6250.
// ---------------------------------------------------------------------------
__global__ __launch_bounds__(512) void k3_final(float* __restrict__ out)
{
    const size_t base = (size_t)blockIdx.x * 1024 + threadIdx.x;  // 2 groups, stride 512

#pragma unroll
    for (int g = 0; g < 2; g++) {
        const size_t i  = base + g * 512;        // 4-elem group index
        const int cbase = (int)(i & 31) * 4;

        uint2 fh = *(const uint2*)(g_featH + i * 4);
        __half2 f01 = *(__half2*)&fh.x;
        __half2 f23 = *(__half2*)&fh.y;
        float f[4] = { __low2float(f01), __high2float(f01),
                       __low2float(f23), __high2float(f23) };
        float acc[4] = { 0.f, 0.f, 0.f, 0.f };

#pragma unroll
        for (int a = 0; a < 3; a++) {
            uint2 h = *(const uint2*)(g_out + (size_t)a * NROWS * CCH + i * 4);
            __half2 h01 = *(__half2*)&h.x;
            __half2 h23 = *(__half2*)&h.y;
            float o[4] = { __low2float(h01), __high2float(h01),
                           __low2float(h23), __high2float(h23) };
#pragma unroll
            for (int j = 0; j < 4; j++) {
                int c = cbase + j;
                float x = fmaf(o[j], g_scale[a * CCH + c], g_off[a * CCH + c]);
                acc[j] += 1.0f / (1.0f + __expf(-x));
            }
        }
        ((float4*)out)[i] = make_float4(acc[0] * f[0], acc[1] * f[1],
                                        acc[2] * f[2], acc[3] * f[3]);
    }
}

// ---------------------------------------------------------------------------
extern "C" void kernel_launch(void* const* d_in, const int* in_sizes, int n_in,
                              void* d_out, int out_size)
{
    const float* feat  = (const float*)d_in[0];
    const int*   nb    = (const int*)  d_in[1];
    const float* W     = (const float*)d_in[2];
    const float* gamma = (const float*)d_in[3];
    const float* beta  = (const float*)d_in[4];

    cudaFuncSetAttribute(k1_gemm, cudaFuncAttributeMaxDynamicSharedMemorySize, DYN_SMEM);

    k0_prep<<<25144, 256>>>(feat, W);            // 25000 feat blocks + 144 W blocks
    dim3 g1(NBLK1, 3);
    k1_gemm<<<g1, 256, DYN_SMEM>>>(nb);
    k2_stats<<<3, 1024>>>(gamma, beta);
    k3_final<<<6250, 512>>>((float*)d_out);      // 6.4M groups / (512 thr * 2)
}

// round 16
// speedup vs baseline: 1.6842x; 1.6842x over previous
#include <cuda_runtime.h>
#include <cuda_fp16.h>
#include <mma.h>
#include <cstdint>

using namespace nvcuda;

#define NROWS  200000
#define CCH    128
#define TM     128
#define TK     64                      // K-chunk (fp16 row = 128B)
#define NCHNK  6                       // K = 384 = 6 x 64
#define NBLK1  1563                    // ceil(200000/128)
#define BN_EPS 1e-5f
#define NCH2   25                      // ceil(1563/64)

#define A_LD   72                      // halves (144B rows)
#define B_LD   136                     // halves (272B rows)
#define A_BYTES (TM * A_LD * 2)        // 18432
#define B_BYTES (TK * B_LD * 2)        // 17408
#define BUF_STRIDE (A_BYTES + B_BYTES) // 35840
#define NSTAGE 3
#define DYN_SMEM (NSTAGE * BUF_STRIDE) // 107520 (fp32 stage 64KB fits inside)

// ---------------- global scratch (allocation-free) ----------------
__device__ __half g_featH[(size_t)NROWS * CCH];          // 51.2 MB fp16 features
__device__ __half g_Wh   [9 * CCH * CCH];                // fp16 W [a*3+seg][k][n]
__device__ __half g_out  [(size_t)3 * NROWS * CCH];      // 153.6 MB fp16 pre-BN outputs
__device__ float  g_part [(size_t)3 * NBLK1 * 2 * CCH];  // per-tile col {sum,sumsq}
__device__ float  g_p2   [3 * NCH2 * 2 * CCH];
__device__ float  g_scale[3 * CCH];                      // rstd*gamma
__device__ float  g_off  [3 * CCH];                      // beta - mu*rstd*gamma

// ---------------- helpers ----------------
__device__ __forceinline__ uint32_t smem_u32(const void* p) {
    return (uint32_t)__cvta_generic_to_shared(p);
}
__device__ __forceinline__ void cp16(uint32_t dst, const void* src, uint32_t sz) {
    asm volatile("cp.async.cg.shared.global [%0], [%1], 16, %2;"
                 :: "r"(dst), "l"(src), "r"(sz) : "memory");
}
__device__ __forceinline__ void cp_commit() {
    asm volatile("cp.async.commit_group;" ::: "memory");
}
__device__ __forceinline__ void cp_wait0() {
    asm volatile("cp.async.wait_group 0;" ::: "memory");
}
__device__ __forceinline__ void cp_wait1() {
    asm volatile("cp.async.wait_group 1;" ::: "memory");
}
__device__ __forceinline__ float fast_sigmoid(float x) {
    float th;
    asm("tanh.approx.f32 %0, %1;" : "=f"(th) : "f"(x * 0.5f));
    return fmaf(th, 0.5f, 0.5f);
}

// ---------------------------------------------------------------------------
// K0: fp32 -> fp16 preconversion for features (blocks < 25000) and W (rest)
// ---------------------------------------------------------------------------
__global__ __launch_bounds__(256) void k0_prep(const float* __restrict__ feat,
                                               const float* __restrict__ W)
{
    size_t i = (size_t)blockIdx.x * 256 + threadIdx.x;
    const size_t nfeat = (size_t)NROWS * CCH / 4;
    const float* src; __half* dst; size_t j;
    if (i < nfeat) { src = feat; dst = g_featH; j = i; }
    else           { src = W;    dst = g_Wh;    j = i - nfeat; if (j >= 9*CCH*CCH/4) return; }
    float4 v = ((const float4*)src)[j];
    __half2 h0 = __floats2half2_rn(v.x, v.y);
    __half2 h1 = __floats2half2_rn(v.z, v.w);
    *(uint2*)(dst + j * 4) = make_uint2(*(uint32_t*)&h0, *(uint32_t*)&h1);
}

// ---------------------------------------------------------------------------
// K1: per (axis, 128-row tile): out = sum_seg gather(A_seg) @ W[a,seg]
// fp16 wmma m16n16k16, K in 6 chunks of 64, 3-stage cp.async pipeline.
// (byte-identical to the 332.5us R11 kernel)
// ---------------------------------------------------------------------------
__global__ void __launch_bounds__(256, 2)
k1_gemm(const int* __restrict__ nb)
{
    const int a    = blockIdx.y;
    const int row0 = blockIdx.x * TM;
    const int t    = threadIdx.x;
    const int warp = t >> 5;
    const int mg   = warp >> 2;     // 0..1 : 64-row half
    const int ng   = warp & 3;      // 0..3 : 32-col group

    extern __shared__ __align__(1024) char dyn[];
    const uint32_t base32 = smem_u32(dyn);

    __shared__ int   s_idx[3][TM];
    __shared__ float Pred[512];

    if (t < TM) {
        int gr = row0 + t;
        bool ok = gr < NROWS;
        s_idx[1][t] = ok ? gr : NROWS;
        s_idx[0][t] = ok ? nb[(size_t)(a * 2 + 0) * NROWS + gr] : NROWS;
        s_idx[2][t] = ok ? nb[(size_t)(a * 2 + 1) * NROWS + gr] : NROWS;
    }
    __syncthreads();

    auto load_chunk = [&](int i) {
        const int seg = i >> 1;
        const int kk  = (i & 1) * TK;
        const int buf = i % NSTAGE;
        const uint32_t abase = base32 + buf * BUF_STRIDE;
        const uint32_t bbase = abase + A_BYTES;
#pragma unroll
        for (int it = 0; it < 4; it++) {
            int vid = t + it * 256;
            int r   = vid >> 3;
            int c   = vid & 7;
            int idx = s_idx[seg][r];
            uint32_t sz = (idx < NROWS) ? 16u : 0u;
            cp16(abase + r * (A_LD * 2) + c * 16,
                 g_featH + (size_t)idx * CCH + kk + c * 8, sz);
        }
        const __half* wsrc = g_Wh + ((size_t)(a * 3 + seg) * CCH + kk) * CCH;
#pragma unroll
        for (int it = 0; it < 4; it++) {
            int vid = t + it * 256;
            int r   = vid >> 4;
            int c   = vid & 15;
            cp16(bbase + r * (B_LD * 2) + c * 16, wsrc + r * CCH + c * 8, 16u);
        }
        cp_commit();
    };

    wmma::fragment<wmma::accumulator, 16, 16, 16, float> acc[4][2];
#pragma unroll
    for (int i = 0; i < 4; i++)
#pragma unroll
        for (int j = 0; j < 2; j++) wmma::fill_fragment(acc[i][j], 0.0f);

    load_chunk(0);
    load_chunk(1);

    for (int i = 0; i < NCHNK; i++) {
        if (i < NCHNK - 1) cp_wait1(); else cp_wait0();
        __syncthreads();
        if (i + 2 < NCHNK) load_chunk(i + 2);

        const int buf = i % NSTAGE;
        const half* As = (const half*)(dyn + buf * BUF_STRIDE);
        const half* Bs = (const half*)(dyn + buf * BUF_STRIDE + A_BYTES);
#pragma unroll
        for (int ks = 0; ks < 4; ks++) {
            wmma::fragment<wmma::matrix_a, 16, 16, 16, half, wmma::row_major> af[4];
#pragma unroll
            for (int q = 0; q < 4; q++)
                wmma::load_matrix_sync(af[q], As + (mg * 64 + q * 16) * A_LD + ks * 16, A_LD);
#pragma unroll
            for (int j = 0; j < 2; j++) {
                wmma::fragment<wmma::matrix_b, 16, 16, 16, half, wmma::row_major> bf;
                wmma::load_matrix_sync(bf, Bs + (ks * 16) * B_LD + ng * 32 + j * 16, B_LD);
#pragma unroll
                for (int q = 0; q < 4; q++)
                    wmma::mma_sync(acc[q][j], af[q], bf, acc[q][j]);
            }
        }
    }
    __syncthreads();

    // ---- epilogue: fp32 stage in smem (reuses pipeline buffers)
    float* stage = (float*)dyn;               // [128][128] fp32 = 64KB
#pragma unroll
    for (int q = 0; q < 4; q++)
#pragma unroll
        for (int j = 0; j < 2; j++)
            wmma::store_matrix_sync(stage + (mg * 64 + q * 16) * CCH + ng * 32 + j * 16,
                                    acc[q][j], CCH, wmma::mem_row_major);
    __syncthreads();

    const int valid = min(TM, NROWS - row0);

    {
        int col = t & 127, part = t >> 7;
        float s = 0.f, s2 = 0.f;
        const float* p = stage + col;
#pragma unroll 8
        for (int r = part * 64; r < part * 64 + 64; r++) {
            float v = p[r * CCH];
            s += v; s2 += v * v;
        }
        Pred[part * 256 + col]       = s;
        Pred[part * 256 + 128 + col] = s2;
    }
    {
        __half* gp = g_out + ((size_t)a * NROWS + row0) * CCH;
#pragma unroll
        for (int it = 0; it < 16; it++) {
            int vid = t + it * 256;
            int r   = vid >> 5;
            int u   = vid & 31;
            if (r < valid) {
                const float* sp = stage + r * CCH + u * 4;
                __half2 h0 = __floats2half2_rn(sp[0], sp[1]);
                __half2 h1 = __floats2half2_rn(sp[2], sp[3]);
                *(uint2*)(gp + (size_t)r * CCH + u * 4) =
                    make_uint2(*(uint32_t*)&h0, *(uint32_t*)&h1);
            }
        }
    }
    __syncthreads();
    if (t < CCH) {
        g_part[(((size_t)a * NBLK1 + blockIdx.x) * 2 + 0) * CCH + t] = Pred[t] + Pred[256 + t];
        g_part[(((size_t)a * NBLK1 + blockIdx.x) * 2 + 1) * CCH + t] = Pred[128 + t] + Pred[384 + t];
    }
}

// ---------------------------------------------------------------------------
// K2a/K2b: deterministic two-stage BN reduction; fold BN into scale/offset
// (byte-identical to R11)
// ---------------------------------------------------------------------------
__global__ __launch_bounds__(256) void k2a()
{
    const int a = blockIdx.x, g = blockIdx.y, t = threadIdx.x;
    const int s = t >> 7, c = t & 127;
    const int b1 = min((g + 1) * 64, NBLK1);
    float acc = 0.f;
    for (int b = g * 64; b < b1; b++)
        acc += g_part[(((size_t)a * NBLK1 + b) * 2 + s) * CCH + c];
    g_p2[((a * NCH2 + g) * 2 + s) * CCH + c] = acc;
}
__global__ __launch_bounds__(128) void k2b(const float* __restrict__ gamma,
                                           const float* __restrict__ beta)
{
    const int a = blockIdx.x, t = threadIdx.x;   // t = channel
    double s = 0.0, s2 = 0.0;
    for (int g = 0; g < NCH2; g++) {
        s  += (double)g_p2[((a * NCH2 + g) * 2 + 0) * CCH + t];
        s2 += (double)g_p2[((a * NCH2 + g) * 2 + 1) * CCH + t];
    }
    double mu  = s / (double)NROWS;
    double var = s2 / (double)NROWS - mu * mu;
    float rstd = rsqrtf((float)var + BN_EPS);
    float sc   = rstd * gamma[a * CCH + t];
    g_scale[a * CCH + t] = sc;
    g_off  [a * CCH + t] = beta[a * CCH + t] - (float)mu * sc;
}

// ---------------------------------------------------------------------------
// K3: out = featH * sum_a sigmoid(o_a * sc[a] + off[a])
// R11 shape (256 threads, 1 group/thread, grid 25000); sigmoid via tanh.approx.
// ---------------------------------------------------------------------------
__global__ __launch_bounds__(256) void k3_final(float* __restrict__ out)
{
    const size_t i  = (size_t)blockIdx.x * 256 + threadIdx.x;  // 4-elem group index
    const int cbase = (int)(i & 31) * 4;

    uint2 fh = *(const uint2*)(g_featH + i * 4);
    __half2 f01 = *(__half2*)&fh.x;
    __half2 f23 = *(__half2*)&fh.y;
    float f[4] = { __low2float(f01), __high2float(f01),
                   __low2float(f23), __high2float(f23) };
    float acc[4] = { 0.f, 0.f, 0.f, 0.f };

#pragma unroll
    for (int a = 0; a < 3; a++) {
        uint2 h = *(const uint2*)(g_out + (size_t)a * NROWS * CCH + i * 4);
        __half2 h01 = *(__half2*)&h.x;
        __half2 h23 = *(__half2*)&h.y;
        float o[4] = { __low2float(h01), __high2float(h01),
                       __low2float(h23), __high2float(h23) };
#pragma unroll
        for (int j = 0; j < 4; j++) {
            int c = cbase + j;
            float x = fmaf(o[j], g_scale[a * CCH + c], g_off[a * CCH + c]);
            acc[j] += fast_sigmoid(x);
        }
    }
    ((float4*)out)[i] = make_float4(acc[0] * f[0], acc[1] * f[1],
                                    acc[2] * f[2], acc[3] * f[3]);
}

// ---------------------------------------------------------------------------
extern "C" void kernel_launch(void* const* d_in, const int* in_sizes, int n_in,
                              void* d_out, int out_size)
{
    const float* feat  = (const float*)d_in[0];
    const int*   nb    = (const int*)  d_in[1];
    const float* W     = (const float*)d_in[2];
    const float* gamma = (const float*)d_in[3];
    const float* beta  = (const float*)d_in[4];

    cudaFuncSetAttribute(k1_gemm, cudaFuncAttributeMaxDynamicSharedMemorySize, DYN_SMEM);

    k0_prep<<<25144, 256>>>(feat, W);            // 25000 feat blocks + 144 W blocks
    dim3 g1(NBLK1, 3);
    k1_gemm<<<g1, 256, DYN_SMEM>>>(nb);
    dim3 g2(3, NCH2);
    k2a<<<g2, 256>>>();
    k2b<<<3, 128>>>(gamma, beta);
    k3_final<<<25000, 256>>>((float*)d_out);
}